// round 1
// baseline (speedup 1.0000x reference)
#include <cuda_runtime.h>
#include <cstdint>

#define MQ   32000
#define HN   32
#define CC   64
#define KK   15
#define COUTN 120

// scratch: sigmoid(mod) per point, (M, 120)
__device__ float g_mod[(size_t)MQ * COUTN];

// ---------------------------------------------------------------------------
// Kernel 1: per-point MLP  mod = sigmoid( leaky(X @ W1 + b1) @ W2 )
// 128 rows per block, weights staged in shared, X row / hidden in registers.
// dyn smem: w1s(4096) + w2s(7680) + b1s(64) + hs(128*64) = 20032 floats = 80128 B
// ---------------------------------------------------------------------------
__global__ __launch_bounds__(128) void mlp_kernel(
    const float* __restrict__ X,
    const float* __restrict__ w1,
    const float* __restrict__ b1,
    const float* __restrict__ w2)
{
    extern __shared__ float sh[];
    float* w1s = sh;                    // 4096
    float* w2s = sh + 4096;             // 7680
    float* b1s = sh + 4096 + 7680;      // 64
    float* hs  = b1s + 64;              // 128*64 = 8192 (layout [j*128 + tid])

    const int tid = threadIdx.x;

    // stage weights (vectorized)
    {
        const float4* w1v = reinterpret_cast<const float4*>(w1);
        float4* w1sv = reinterpret_cast<float4*>(w1s);
        for (int i = tid; i < 4096 / 4; i += 128) w1sv[i] = w1v[i];
        const float4* w2v = reinterpret_cast<const float4*>(w2);
        float4* w2sv = reinterpret_cast<float4*>(w2s);
        for (int i = tid; i < 7680 / 4; i += 128) w2sv[i] = w2v[i];
        if (tid < 64) b1s[tid] = b1[tid];
    }
    __syncthreads();

    const int r = blockIdx.x * 128 + tid;   // 250 * 128 = 32000 exact

    // X row into registers
    float x[64];
    {
        const float4* xv = reinterpret_cast<const float4*>(X + (size_t)r * 64);
#pragma unroll
        for (int i = 0; i < 16; i++) {
            float4 v = xv[i];
            x[4*i+0] = v.x; x[4*i+1] = v.y; x[4*i+2] = v.z; x[4*i+3] = v.w;
        }
    }

    // hidden = leaky(x @ W1 + b1), 4 outputs per pass, staged to shared
    for (int j = 0; j < 64; j += 4) {
        float a0 = b1s[j+0], a1 = b1s[j+1], a2 = b1s[j+2], a3 = b1s[j+3];
#pragma unroll
        for (int c = 0; c < 64; c++) {
            float xc = x[c];
            float4 w = *reinterpret_cast<const float4*>(&w1s[c*64 + j]);
            a0 = fmaf(xc, w.x, a0);
            a1 = fmaf(xc, w.y, a1);
            a2 = fmaf(xc, w.z, a2);
            a3 = fmaf(xc, w.w, a3);
        }
        a0 = (a0 >= 0.f) ? a0 : 0.1f * a0;
        a1 = (a1 >= 0.f) ? a1 : 0.1f * a1;
        a2 = (a2 >= 0.f) ? a2 : 0.1f * a2;
        a3 = (a3 >= 0.f) ? a3 : 0.1f * a3;
        hs[(j+0)*128 + tid] = a0;
        hs[(j+1)*128 + tid] = a1;
        hs[(j+2)*128 + tid] = a2;
        hs[(j+3)*128 + tid] = a3;
    }

    // reload hidden to registers (own data, no sync needed)
    float h[64];
#pragma unroll
    for (int j = 0; j < 64; j++) h[j] = hs[j*128 + tid];

    // mod = sigmoid(h @ W2)
    float* op = g_mod + (size_t)r * COUTN;
    for (int o = 0; o < COUTN; o += 4) {
        float a0 = 0.f, a1 = 0.f, a2 = 0.f, a3 = 0.f;
#pragma unroll
        for (int j = 0; j < 64; j++) {
            float hj = h[j];
            float4 w = *reinterpret_cast<const float4*>(&w2s[j*COUTN + o]);
            a0 = fmaf(hj, w.x, a0);
            a1 = fmaf(hj, w.y, a1);
            a2 = fmaf(hj, w.z, a2);
            a3 = fmaf(hj, w.w, a3);
        }
        float4 v;
        v.x = 1.f / (1.f + __expf(-a0));
        v.y = 1.f / (1.f + __expf(-a1));
        v.z = 1.f / (1.f + __expf(-a2));
        v.w = 1.f / (1.f + __expf(-a3));
        *reinterpret_cast<float4*>(op + o) = v;
    }
}

// ---------------------------------------------------------------------------
// Kernel 2: geometry (argmin over 15 kernel points + linear influence) and
// gather-weighted reduction. One 64-thread block per query point m;
// warp 0 handles the 32 neighbors' geometry, all 64 threads own one channel.
// ---------------------------------------------------------------------------
__global__ __launch_bounds__(64) void kp_kernel(
    const float* __restrict__ q_pts,
    const float* __restrict__ s_pts,
    const float* __restrict__ s_feats,
    const int*   __restrict__ nidx,
    const float* __restrict__ kpts,
    const float* __restrict__ W,
    float* __restrict__ out)
{
    __shared__ float sh_kp[45];
    __shared__ int   sh_pk[32];      // (k << 26) | (ind * 64)
    __shared__ float sh_infl[32];
    __shared__ float sh_mod[120];
    __shared__ float sh_wm[15 * 64]; // weights[k,c] * mod[k, c>>3]

    const int m   = blockIdx.x;
    const int tid = threadIdx.x;

    if (tid < 45) sh_kp[tid] = kpts[tid];
    for (int i = tid; i < 120; i += 64) sh_mod[i] = g_mod[(size_t)m * 120 + i];
    __syncthreads();

    if (tid < 32) {
        int ind = nidx[m * HN + tid];
        float qx = q_pts[m*3+0], qy = q_pts[m*3+1], qz = q_pts[m*3+2];
        float nx = s_pts[ind*3+0] - qx;
        float ny = s_pts[ind*3+1] - qy;
        float nz = s_pts[ind*3+2] - qz;
        float best = 3.4e38f; int bk = 0;
#pragma unroll
        for (int k = 0; k < 15; k++) {
            float dx = nx - sh_kp[k*3+0];
            float dy = ny - sh_kp[k*3+1];
            float dz = nz - sh_kp[k*3+2];
            float d2 = fmaf(dx, dx, fmaf(dy, dy, dz*dz));
            if (d2 < best) { best = d2; bk = k; }   // strict < : first min (matches argmin)
        }
        sh_infl[tid] = fmaxf(0.f, 1.f - sqrtf(best));
        sh_pk[tid]   = (bk << 26) | (ind * 64);
    }

    // per-channel modulated weights (shared to avoid dynamic reg indexing)
    const int c = tid;
#pragma unroll
    for (int k = 0; k < 15; k++)
        sh_wm[k*64 + c] = W[k*64 + c] * sh_mod[k*8 + (c >> 3)];
    __syncthreads();

    float acc0 = 0.f, acc1 = 0.f;
#pragma unroll
    for (int h = 0; h < 32; h += 2) {
        int   pk0 = sh_pk[h],     pk1 = sh_pk[h+1];
        float s0  = sh_infl[h],   s1  = sh_infl[h+1];
        float f0  = __ldg(&s_feats[(pk0 & 0x03FFFFFF) + c]);
        float f1  = __ldg(&s_feats[(pk1 & 0x03FFFFFF) + c]);
        acc0 = fmaf(f0, sh_wm[(pk0 >> 26) * 64 + c] * s0, acc0);
        acc1 = fmaf(f1, sh_wm[(pk1 >> 26) * 64 + c] * s1, acc1);
    }
    out[(size_t)m * 64 + c] = acc0 + acc1;
}

// ---------------------------------------------------------------------------
extern "C" void kernel_launch(void* const* d_in, const int* in_sizes, int n_in,
                              void* d_out, int out_size)
{
    const float* q_pts   = (const float*)d_in[0];
    const float* s_pts   = (const float*)d_in[1];
    const float* s_feats = (const float*)d_in[2];
    const int*   nidx    = (const int*)  d_in[3];
    const float* kpts    = (const float*)d_in[4];
    const float* W       = (const float*)d_in[5];
    const float* w1      = (const float*)d_in[6];
    const float* b1      = (const float*)d_in[7];
    const float* w2      = (const float*)d_in[8];
    float* out = (float*)d_out;

    const int smem = 20032 * 4;  // 80128 B
    cudaFuncSetAttribute(mlp_kernel, cudaFuncAttributeMaxDynamicSharedMemorySize, smem);

    mlp_kernel<<<MQ / 128, 128, smem>>>(s_feats, w1, b1, w2);
    kp_kernel<<<MQ, 64>>>(q_pts, s_pts, s_feats, nidx, kpts, W, out);
}

// round 2
// speedup vs baseline: 1.2229x; 1.2229x over previous
#include <cuda_runtime.h>
#include <cstdint>

#define MQ   32000
#define HN   32
#define CC   64
#define KK   15
#define COUTN 120

// scratch
__device__ float  g_mod[(size_t)MQ * COUTN];   // sigmoid(mod), (M,120)
__device__ float4 g_pts4[MQ];                   // padded s_pts

// ---------------------------------------------------------------------------
// Kernel 1: per-point MLP  mod = sigmoid( leaky(X @ W1 + b1) @ W2 )
// 256 threads/block, 256 rows/block, 125 blocks. Also repacks s_pts -> float4.
// dyn smem floats: w1s 4096 + w2s 7680 + b1s 64 + hs 16384 = 28224 (112896 B)
// ---------------------------------------------------------------------------
__global__ __launch_bounds__(256) void mlp_kernel(
    const float* __restrict__ X,
    const float* __restrict__ w1,
    const float* __restrict__ b1,
    const float* __restrict__ w2,
    const float* __restrict__ s_pts)
{
    extern __shared__ float sh[];
    float* w1s = sh;                    // 4096
    float* w2s = sh + 4096;             // 7680
    float* b1s = sh + 4096 + 7680;      // 64
    float* hs  = b1s + 64;              // 256*64, layout [j*256 + tid]

    const int tid = threadIdx.x;
    const int r   = blockIdx.x * 256 + tid;   // 125*256 = 32000 exact

    // fused: repack this block's 256 s_pts rows into float4 (staging via hs)
    {
        const int base = blockIdx.x * 256;
        for (int i = tid; i < 768; i += 256) hs[i] = s_pts[base * 3 + i];
        __syncthreads();
        float4 v;
        v.x = hs[tid * 3 + 0]; v.y = hs[tid * 3 + 1]; v.z = hs[tid * 3 + 2]; v.w = 0.f;
        g_pts4[r] = v;
        __syncthreads();
    }

    // stage weights (vectorized)
    {
        const float4* w1v = reinterpret_cast<const float4*>(w1);
        float4* w1sv = reinterpret_cast<float4*>(w1s);
        for (int i = tid; i < 4096 / 4; i += 256) w1sv[i] = w1v[i];
        const float4* w2v = reinterpret_cast<const float4*>(w2);
        float4* w2sv = reinterpret_cast<float4*>(w2s);
        for (int i = tid; i < 7680 / 4; i += 256) w2sv[i] = w2v[i];
        if (tid < 64) b1s[tid] = b1[tid];
    }
    __syncthreads();

    // X row into registers
    float x[64];
    {
        const float4* xv = reinterpret_cast<const float4*>(X + (size_t)r * 64);
#pragma unroll
        for (int i = 0; i < 16; i++) {
            float4 v = xv[i];
            x[4*i+0] = v.x; x[4*i+1] = v.y; x[4*i+2] = v.z; x[4*i+3] = v.w;
        }
    }

    // hidden = leaky(x @ W1 + b1), 4 outputs per pass, staged to shared
    for (int j = 0; j < 64; j += 4) {
        float a0 = b1s[j+0], a1 = b1s[j+1], a2 = b1s[j+2], a3 = b1s[j+3];
#pragma unroll
        for (int c = 0; c < 64; c++) {
            float xc = x[c];
            float4 w = *reinterpret_cast<const float4*>(&w1s[c*64 + j]);
            a0 = fmaf(xc, w.x, a0);
            a1 = fmaf(xc, w.y, a1);
            a2 = fmaf(xc, w.z, a2);
            a3 = fmaf(xc, w.w, a3);
        }
        a0 = (a0 >= 0.f) ? a0 : 0.1f * a0;
        a1 = (a1 >= 0.f) ? a1 : 0.1f * a1;
        a2 = (a2 >= 0.f) ? a2 : 0.1f * a2;
        a3 = (a3 >= 0.f) ? a3 : 0.1f * a3;
        hs[(j+0)*256 + tid] = a0;
        hs[(j+1)*256 + tid] = a1;
        hs[(j+2)*256 + tid] = a2;
        hs[(j+3)*256 + tid] = a3;
    }

    // reload hidden to registers (own data, no sync needed)
    float h[64];
#pragma unroll
    for (int j = 0; j < 64; j++) h[j] = hs[j*256 + tid];

    // mod = sigmoid(h @ W2)
    float* op = g_mod + (size_t)r * COUTN;
    for (int o = 0; o < COUTN; o += 4) {
        float a0 = 0.f, a1 = 0.f, a2 = 0.f, a3 = 0.f;
#pragma unroll
        for (int j = 0; j < 64; j++) {
            float hj = h[j];
            float4 w = *reinterpret_cast<const float4*>(&w2s[j*COUTN + o]);
            a0 = fmaf(hj, w.x, a0);
            a1 = fmaf(hj, w.y, a1);
            a2 = fmaf(hj, w.z, a2);
            a3 = fmaf(hj, w.w, a3);
        }
        float4 v;
        v.x = 1.f / (1.f + __expf(-a0));
        v.y = 1.f / (1.f + __expf(-a1));
        v.z = 1.f / (1.f + __expf(-a2));
        v.w = 1.f / (1.f + __expf(-a3));
        *reinterpret_cast<float4*>(op + o) = v;
    }
}

// ---------------------------------------------------------------------------
// Kernel 2: warp-per-query geometry + gather-weighted reduction.
// 256 threads = 8 warps = 8 queries/block, 4000 blocks.
// Lane = one neighbor for geometry; pk/infl broadcast via shfl.
// Channel phase: lane owns 4 channels; half-warps process 2 neighbors/iter.
// ---------------------------------------------------------------------------
__global__ __launch_bounds__(256) void kp_kernel(
    const float* __restrict__ q_pts,
    const float* __restrict__ s_feats,
    const int*   __restrict__ nidx,
    const float* __restrict__ kpts,
    const float* __restrict__ Wg,
    float* __restrict__ out)
{
    __shared__ float sW[15 * 72];    // padded stride 72 (bank-conflict break)
    __shared__ float skp[45];
    __shared__ float smod[8][120];

    const int tid  = threadIdx.x;
    const int wid  = tid >> 5;
    const int lane = tid & 31;
    const int m    = blockIdx.x * 8 + wid;
    const unsigned FULL = 0xffffffffu;

    for (int i = tid; i < 960; i += 256) sW[(i >> 6) * 72 + (i & 63)] = Wg[i];
    if (tid < 45) skp[tid] = kpts[tid];
    for (int i = lane; i < 120; i += 32) smod[wid][i] = g_mod[(size_t)m * 120 + i];
    __syncthreads();

    // geometry: one neighbor per lane
    const int ind = nidx[m * HN + lane];
    const float qx = q_pts[m*3+0], qy = q_pts[m*3+1], qz = q_pts[m*3+2];
    float4 p = g_pts4[ind];
    const float nx = p.x - qx, ny = p.y - qy, nz = p.z - qz;
    float best = 3.4e38f; int bk = 0;
#pragma unroll
    for (int k = 0; k < 15; k++) {
        float dx = nx - skp[k*3+0];
        float dy = ny - skp[k*3+1];
        float dz = nz - skp[k*3+2];
        float d2 = fmaf(dx, dx, fmaf(dy, dy, dz*dz));
        if (d2 < best) { best = d2; bk = k; }   // strict <: first-min like argmin
    }
    const float infl = fmaxf(0.f, 1.f - sqrtf(best));
    const int pk = (bk << 26) | (ind << 6);     // ind*64 < 2^21, k in bits 26..29

    // accumulation: half-warp g handles neighbors 2t+g; lane owns 4 channels
    const int g  = lane >> 4;
    const int cl = (lane & 15) << 2;
    float4 acc = make_float4(0.f, 0.f, 0.f, 0.f);
#pragma unroll
    for (int t = 0; t < 16; t++) {
        const int   h   = 2 * t + g;
        const int   pkh = __shfl_sync(FULL, pk,   h);
        const float s   = __shfl_sync(FULL, infl, h);
        const int   k   = pkh >> 26;
        const int   row = pkh & 0x03FFFFFF;
        const float4 f = *reinterpret_cast<const float4*>(s_feats + row + cl);
        const float4 w = *reinterpret_cast<const float4*>(&sW[k * 72 + cl]);
        const float sc = smod[wid][(k << 3) + (cl >> 3)] * s;
        acc.x = fmaf(f.x, w.x * sc, acc.x);
        acc.y = fmaf(f.y, w.y * sc, acc.y);
        acc.z = fmaf(f.z, w.z * sc, acc.z);
        acc.w = fmaf(f.w, w.w * sc, acc.w);
    }
    // combine even/odd-neighbor halves (lanes L and L+16 own same channels)
    acc.x += __shfl_xor_sync(FULL, acc.x, 16);
    acc.y += __shfl_xor_sync(FULL, acc.y, 16);
    acc.z += __shfl_xor_sync(FULL, acc.z, 16);
    acc.w += __shfl_xor_sync(FULL, acc.w, 16);
    if (g == 0)
        *reinterpret_cast<float4*>(out + (size_t)m * 64 + cl) = acc;
}

// ---------------------------------------------------------------------------
extern "C" void kernel_launch(void* const* d_in, const int* in_sizes, int n_in,
                              void* d_out, int out_size)
{
    const float* q_pts   = (const float*)d_in[0];
    const float* s_pts   = (const float*)d_in[1];
    const float* s_feats = (const float*)d_in[2];
    const int*   nidx    = (const int*)  d_in[3];
    const float* kpts    = (const float*)d_in[4];
    const float* W       = (const float*)d_in[5];
    const float* w1      = (const float*)d_in[6];
    const float* b1      = (const float*)d_in[7];
    const float* w2      = (const float*)d_in[8];
    float* out = (float*)d_out;

    const int smem = 28224 * 4;  // 112896 B
    cudaFuncSetAttribute(mlp_kernel, cudaFuncAttributeMaxDynamicSharedMemorySize, smem);

    mlp_kernel<<<MQ / 256, 256, smem>>>(s_feats, w1, b1, w2, s_pts);
    kp_kernel<<<MQ / 8, 256>>>(q_pts, s_feats, nidx, kpts, W, out);
}